// round 3
// baseline (speedup 1.0000x reference)
#include <cuda_runtime.h>
#include <cuda_bf16.h>

// HH neuron network, N=4096, 1000 steps.
// s has no V-feedback -> s_k = s0 * decay^(k+1); the O(N^2) synaptic sum
// collapses to 6 per-step dot products against b[t][j] = s0[t][j]*cols[t][j].
// CRITICAL: reference does nan_to_num(clip(V)) -> NaN maps to 0, not to a rail.
// The dynamics blow up (m gate diverges at V=-100), so this path IS taken.

#define Nn        4096
#define NTHREADS  512
#define NPT       8            // neurons per thread (512*8 = 4096)
#define NWARPS    (NTHREADS/32)
#define ROWCHUNKS 64
#define DTc       0.01f

__device__ float g_part[(size_t)ROWCHUNKS * 6 * Nn];
__device__ float g_b[6 * Nn];

// ---------------------------------------------------------------------------
// Setup 1: partial per-type masked column sums of W.
// ---------------------------------------------------------------------------
__global__ void k_cols_partial(const float* __restrict__ W,
                               const int*   __restrict__ Ty) {
    const int j  = blockIdx.x * blockDim.x + threadIdx.x;
    const int r0 = blockIdx.y * (Nn / ROWCHUNKS);
    float s0_ = 0.f, s1_ = 0.f, s2_ = 0.f, s3_ = 0.f, s4_ = 0.f, s5_ = 0.f;
    for (int r = r0; r < r0 + Nn / ROWCHUNKS; ++r) {
        size_t idx = (size_t)r * Nn + j;
        float w = W[idx];
        int   t = Ty[idx];
        s0_ += (t == 1) ? w : 0.f;
        s1_ += (t == 2) ? w : 0.f;
        s2_ += (t == 3) ? w : 0.f;
        s3_ += (t == 4) ? w : 0.f;
        s4_ += (t == 5) ? w : 0.f;
        s5_ += (t == 6) ? w : 0.f;
    }
    float* base = g_part + (size_t)blockIdx.y * 6 * Nn;
    base[0 * Nn + j] = s0_;
    base[1 * Nn + j] = s1_;
    base[2 * Nn + j] = s2_;
    base[3 * Nn + j] = s3_;
    base[4 * Nn + j] = s4_;
    base[5 * Nn + j] = s5_;
}

// ---------------------------------------------------------------------------
// Setup 2: b[t][j] = (sum of partials) * s0[t][j]
// ---------------------------------------------------------------------------
__global__ void k_build_b(const float* __restrict__ s0) {
    int idx = blockIdx.x * blockDim.x + threadIdx.x;
    if (idx >= 6 * Nn) return;
    float acc = 0.f;
#pragma unroll 8
    for (int c = 0; c < ROWCHUNKS; ++c)
        acc += g_part[(size_t)c * 6 * Nn + idx];
    g_b[idx] = acc * s0[idx];
}

__device__ __forceinline__ void warp_reduce6(float* p) {
#pragma unroll
    for (int o = 16; o > 0; o >>= 1) {
#pragma unroll
        for (int t = 0; t < 6; ++t)
            p[t] += __shfl_xor_sync(0xffffffffu, p[t], o);
    }
}

// ---------------------------------------------------------------------------
// Persistent single-CTA time stepper.
// ---------------------------------------------------------------------------
__global__ __launch_bounds__(NTHREADS, 1)
void k_hh(const float* __restrict__ Iext_g, const float* __restrict__ V0,
          const float* __restrict__ m0,     const float* __restrict__ h0,
          const float* __restrict__ n0,     float* __restrict__ out, int steps) {
    __shared__ float wpart[NWARPS][8];
    __shared__ float Bsh[8];
    __shared__ float dk_sh[8];
    __shared__ float Isyn_sh;

    const int tid  = threadIdx.x;
    const int lane = tid & 31;
    const int wid  = tid >> 5;
    const int j0   = tid * NPT;

    float b[6][NPT];
#pragma unroll
    for (int t = 0; t < 6; ++t) {
#pragma unroll
        for (int q = 0; q < NPT / 4; ++q) {
            float4 v = *reinterpret_cast<const float4*>(&g_b[t * Nn + j0 + 4 * q]);
            b[t][4 * q + 0] = v.x; b[t][4 * q + 1] = v.y;
            b[t][4 * q + 2] = v.z; b[t][4 * q + 3] = v.w;
        }
    }
    float V[NPT], m_[NPT], h_[NPT], n_[NPT], Ie[NPT];
#pragma unroll
    for (int q = 0; q < NPT / 4; ++q) {
        float4 a;
        a = *reinterpret_cast<const float4*>(V0 + j0 + 4 * q);
        V[4*q]=a.x; V[4*q+1]=a.y; V[4*q+2]=a.z; V[4*q+3]=a.w;
        a = *reinterpret_cast<const float4*>(m0 + j0 + 4 * q);
        m_[4*q]=a.x; m_[4*q+1]=a.y; m_[4*q+2]=a.z; m_[4*q+3]=a.w;
        a = *reinterpret_cast<const float4*>(h0 + j0 + 4 * q);
        h_[4*q]=a.x; h_[4*q+1]=a.y; h_[4*q+2]=a.z; h_[4*q+3]=a.w;
        a = *reinterpret_cast<const float4*>(n0 + j0 + 4 * q);
        n_[4*q]=a.x; n_[4*q+1]=a.y; n_[4*q+2]=a.z; n_[4*q+3]=a.w;
        a = *reinterpret_cast<const float4*>(Iext_g + j0 + 4 * q);
        Ie[4*q]=a.x; Ie[4*q+1]=a.y; Ie[4*q+2]=a.z; Ie[4*q+3]=a.w;
    }

    // one-time B[t] = sum_j b[t][j]
    {
        float p[6];
#pragma unroll
        for (int t = 0; t < 6; ++t) {
            p[t] = 0.f;
#pragma unroll
            for (int nn = 0; nn < NPT; ++nn) p[t] += b[t][nn];
        }
        warp_reduce6(p);
        if (lane == 0)
#pragma unroll
            for (int t = 0; t < 6; ++t) wpart[wid][t] = p[t];
        __syncthreads();
        if (wid == 0) {
            float q[6];
#pragma unroll
            for (int t = 0; t < 6; ++t) q[t] = (lane < NWARPS) ? wpart[lane][t] : 0.f;
            warp_reduce6(q);
            if (lane == 0) {
#pragma unroll
                for (int t = 0; t < 6; ++t) { Bsh[t] = q[t]; dk_sh[t] = 1.f; }
            }
        }
        __syncthreads();
    }

    for (int k = 0; k < steps; ++k) {
        // dot partials p[t] = sum b[t][j]*V[j]
        float p[6];
#pragma unroll
        for (int t = 0; t < 6; ++t) {
            p[t] = 0.f;
#pragma unroll
            for (int nn = 0; nn < NPT; ++nn) p[t] = fmaf(b[t][nn], V[nn], p[t]);
        }
        warp_reduce6(p);
        if (lane == 0)
#pragma unroll
            for (int t = 0; t < 6; ++t) wpart[wid][t] = p[t];
        __syncthreads();

        // warp 0: final reduce + scalar Isyn (overlaps with HH math below)
        if (tid < 32) {
            float q[6];
#pragma unroll
            for (int t = 0; t < 6; ++t) q[t] = (lane < NWARPS) ? wpart[lane][t] : 0.f;
            warp_reduce6(q);
            if (lane == 0) {
                const float ESYN[6] = {0.f, -70.f, -90.f, 0.f, 0.f, 0.f};
                const float SGN[6]  = {-1.f, 1.f, 1.f, -1.f, -1.f, -1.f};
                const float DEC[6]  = {1.0f - 0.01f / 2.0f,   1.0f - 0.01f / 5.0f,
                                       1.0f - 0.01f / 10.0f,  1.0f - 0.01f / 100.0f,
                                       1.0f - 0.01f / 50.0f,  1.0f - 0.01f / 30.0f};
                float Is = 0.f;
#pragma unroll
                for (int t = 0; t < 6; ++t) {
                    float dk = dk_sh[t] * DEC[t];
                    dk_sh[t] = dk;
                    float It = 0.1f * dk * (q[t] - ESYN[t] * Bsh[t]);
                    Is += SGN[t] * It;
                }
                Isyn_sh = Is;
            }
        }

        // HH gate math at current V (independent of Isyn).
        // Mirror reference expression forms; NaN/inf must propagate like jnp.
        float hhcur[NPT];
#pragma unroll
        for (int nn = 0; nn < NPT; ++nn) {
            float v  = V[nn];
            float e1 = __expf(1.0f - 0.1f * v);              // exp(1-0.1V)
            float e2 = __expf(-v * (1.0f / 18.0f));
            float e3 = __expf(-v * 0.05f);
            float e4 = __expf(-v * 0.0125f);
            // exp(2.5-0.1V)=e^1.5*e1 ; exp(3-0.1V)=e^2*e1
            float am = __fdividef(2.5f - 0.1f * v, fmaf(4.481689070338065f, e1, -1.0f));
            float bm = 4.0f * e2;
            float ah = 0.07f * e3;
            float bh = __fdividef(1.0f, fmaf(7.38905609893065f, e1, 1.0f));
            float an = __fdividef(0.1f - 0.01f * v, e1 - 1.0f);
            float bn = 0.125f * e4;
            float mm = m_[nn];
            mm = mm + DTc * (am * (1.0f - mm) - bm * mm);    // ref form (NaN at mm=inf)
            m_[nn] = mm;
            float hh = h_[nn];
            hh = hh + DTc * (ah * (1.0f - hh) - bh * hh);
            h_[nn] = hh;
            float nv = n_[nn];
            nv = nv + DTc * (an * (1.0f - nv) - bn * nv);
            n_[nn] = nv;
            float INa = 120.0f * mm * mm * mm * hh * (v - 50.0f);
            float n2  = nv * nv;
            float IK  = 36.0f * n2 * n2 * (v + 77.0f);
            float IL  = 0.3f * (v + 54.387f);
            hhcur[nn] = INa + IK + IL;
        }
        __syncthreads();

        const float Is = Isyn_sh;
#pragma unroll
        for (int nn = 0; nn < NPT; ++nn) {
            float Ipre = Ie[nn] + Is;
            float vn = V[nn] + DTc * (Ipre - hhcur[nn]);
            // jnp semantics: clip(+-inf)->+-100, then nan_to_num: NaN->0.
            unsigned u = __float_as_uint(vn) & 0x7fffffffu;
            if (u > 0x7f800000u) vn = 0.0f;                   // NaN (fast-math-proof)
            else                 vn = fminf(fmaxf(vn, -100.0f), 100.0f);
            V[nn] = vn;
        }
        float* orow = out + (size_t)k * Nn + j0;
#pragma unroll
        for (int q = 0; q < NPT / 4; ++q) {
            float4 o = make_float4(V[4*q], V[4*q+1], V[4*q+2], V[4*q+3]);
            *reinterpret_cast<float4*>(orow + 4 * q) = o;
        }
    }
}

// ---------------------------------------------------------------------------
extern "C" void kernel_launch(void* const* d_in, const int* in_sizes, int n_in,
                              void* d_out, int out_size) {
    const float* I_ext = (const float*)d_in[0];
    const float* W     = (const float*)d_in[1];
    const float* V0    = (const float*)d_in[2];
    const float* m0    = (const float*)d_in[3];
    const float* h0    = (const float*)d_in[4];
    const float* n0    = (const float*)d_in[5];
    const float* s0    = (const float*)d_in[6];
    const int*   Ty    = (const int*)d_in[7];
    float* out = (float*)d_out;

    const int steps = out_size / Nn;   // 1000

    dim3 g1(Nn / 256, ROWCHUNKS);
    k_cols_partial<<<g1, 256>>>(W, Ty);
    k_build_b<<<(6 * Nn + 255) / 256, 256>>>(s0);
    k_hh<<<1, NTHREADS>>>(I_ext, V0, m0, h0, n0, out, steps);
}

// round 5
// speedup vs baseline: 2.1515x; 2.1515x over previous
#include <cuda_runtime.h>
#include <cuda_bf16.h>
#include <cstdint>

// HH neuron network, N=4096, 1000 steps.
// s has no V-feedback -> O(N^2) collapses to 6 dots vs b[t][j]=s0*cols.
// R4: split the sequential stepper across 8 SMs (cluster) with a 1-scalar-
// per-CTA DSMEM all-reduce per step. Per-neuron gate math identical to the
// R3 passing kernel (NaN onset must match reference exactly).

#define Nn        4096
#define CLUSTERS  8
#define CTHREADS  512
#define NWARPS    (CTHREADS/32)
#define ROWCHUNKS 64
#define DTc       0.01f

__device__ float g_part[(size_t)ROWCHUNKS * 6 * Nn];
__device__ float g_b[6 * Nn];

// ---------------------------------------------------------------------------
// Setup 1: partial per-type masked column sums of W (float4/int4 vectorized).
// ---------------------------------------------------------------------------
__global__ void k_cols_partial(const float4* __restrict__ W4,
                               const int4*   __restrict__ Ty4) {
    const int j4 = blockIdx.x * blockDim.x + threadIdx.x;   // float4 col index
    const int r0 = blockIdx.y * (Nn / ROWCHUNKS);
    float acc[6][4];
#pragma unroll
    for (int t = 0; t < 6; ++t)
#pragma unroll
        for (int c = 0; c < 4; ++c) acc[t][c] = 0.f;

    for (int r = r0; r < r0 + Nn / ROWCHUNKS; ++r) {
        size_t idx = (size_t)r * (Nn / 4) + j4;
        float4 w = W4[idx];
        int4   t = Ty4[idx];
        const float wv[4] = {w.x, w.y, w.z, w.w};
        const int   tv[4] = {t.x, t.y, t.z, t.w};
#pragma unroll
        for (int c = 0; c < 4; ++c)
#pragma unroll
            for (int tt = 0; tt < 6; ++tt)
                acc[tt][c] += (tv[c] == tt + 1) ? wv[c] : 0.f;
    }
    float* base = g_part + (size_t)blockIdx.y * 6 * Nn;
#pragma unroll
    for (int t = 0; t < 6; ++t) {
        float4 o = make_float4(acc[t][0], acc[t][1], acc[t][2], acc[t][3]);
        *reinterpret_cast<float4*>(base + t * Nn + 4 * j4) = o;
    }
}

// ---------------------------------------------------------------------------
// Setup 2: b[t][j] = (sum of partials) * s0[t][j]
// ---------------------------------------------------------------------------
__global__ void k_build_b(const float* __restrict__ s0) {
    int idx = blockIdx.x * blockDim.x + threadIdx.x;
    if (idx >= 6 * Nn) return;
    float acc = 0.f;
#pragma unroll 8
    for (int c = 0; c < ROWCHUNKS; ++c)
        acc += g_part[(size_t)c * 6 * Nn + idx];
    g_b[idx] = acc * s0[idx];
}

// ---------------------------------------------------------------------------
__device__ __forceinline__ void warp_reduce6(float* p) {
#pragma unroll
    for (int o = 16; o > 0; o >>= 1) {
#pragma unroll
        for (int t = 0; t < 6; ++t)
            p[t] += __shfl_xor_sync(0xffffffffu, p[t], o);
    }
}

__device__ __forceinline__ uint32_t smem_u32(const void* p) {
    return (uint32_t)__cvta_generic_to_shared(p);
}
__device__ __forceinline__ void dsmem_st(uint32_t laddr, unsigned rank, float v) {
    uint32_t r;
    asm volatile("mapa.shared::cluster.u32 %0, %1, %2;" : "=r"(r) : "r"(laddr), "r"(rank));
    asm volatile("st.shared::cluster.f32 [%0], %1;" :: "r"(r), "f"(v) : "memory");
}

// ---------------------------------------------------------------------------
// Cluster-of-8 persistent time stepper. 1 neuron/thread.
// ---------------------------------------------------------------------------
__global__ __cluster_dims__(CLUSTERS, 1, 1) __launch_bounds__(CTHREADS, 1)
void k_hh(const float* __restrict__ Iext_g, const float* __restrict__ V0,
          const float* __restrict__ m0,     const float* __restrict__ h0,
          const float* __restrict__ n0,     float* __restrict__ out, int steps) {
    __shared__ float wpart[NWARPS][8];
    __shared__ float slot[2][8];      // [parity][source rank] weighted scalars
    __shared__ float Bslot[8][8];     // one-time B exchange: [rank][t]

    const int tid  = threadIdx.x;
    const int lane = tid & 31;
    const int wid  = tid >> 5;
    unsigned rank;
    asm("mov.u32 %0, %%cluster_ctarank;" : "=r"(rank));
    const int j = (int)rank * CTHREADS + tid;   // my neuron

    // per-thread state (1 neuron)
    float b[6];
#pragma unroll
    for (int t = 0; t < 6; ++t) b[t] = g_b[t * Nn + j];
    float V  = V0[j], mM = m0[j], hH = h0[j], nN = n0[j], Ie = Iext_g[j];

    const float DEC[6] = {1.0f - 0.01f / 2.0f,   1.0f - 0.01f / 5.0f,
                          1.0f - 0.01f / 10.0f,  1.0f - 0.01f / 100.0f,
                          1.0f - 0.01f / 50.0f,  1.0f - 0.01f / 30.0f};
    const float SGN[6] = {-1.f, 1.f, 1.f, -1.f, -1.f, -1.f};

    // ---- one-time: B[t] = sum_j b[t][j] across the whole cluster ----
    {
        float p[6];
#pragma unroll
        for (int t = 0; t < 6; ++t) p[t] = b[t];
        warp_reduce6(p);
        if (lane == 0)
#pragma unroll
            for (int t = 0; t < 6; ++t) wpart[wid][t] = p[t];
        __syncthreads();
        if (wid == 0) {
            float q[6];
#pragma unroll
            for (int t = 0; t < 6; ++t) q[t] = (lane < NWARPS) ? wpart[lane][t] : 0.f;
            warp_reduce6(q);
            if (lane < CLUSTERS) {
                // store my CTA's 6 partials into CTA `lane`'s Bslot[rank][*]
#pragma unroll
                for (int t = 0; t < 6; ++t)
                    dsmem_st(smem_u32(&Bslot[rank][t]), lane, q[t]);
            }
        }
        asm volatile("barrier.cluster.arrive.aligned;" ::: "memory");
        asm volatile("barrier.cluster.wait.aligned;"   ::: "memory");
    }
    float B1 = 0.f, B2 = 0.f;
#pragma unroll
    for (int r = 0; r < CLUSTERS; ++r) { B1 += Bslot[r][1]; B2 += Bslot[r][2]; }

    // per-thread decay recurrences
    float u1 = 7.0f * B1;          // -> G term 7*dk1*B1 (GABAa: +0.1*70)
    float u2 = 9.0f * B2;          //           9*dk2*B2 (GABAb: +0.1*90)
    float c1[6];
#pragma unroll
    for (int t = 0; t < 6; ++t) c1[t] = SGN[t] * 0.1f;   // will be *= DEC each step

    for (int k = 0; k < steps; ++k) {
        const int par = k & 1;
        // decay update (dk = DEC^(k+1), matching ref's s *= decay before use)
#pragma unroll
        for (int t = 0; t < 6; ++t) c1[t] *= DEC[t];
        u1 *= DEC[1];
        u2 *= DEC[2];

        // dot partials p[t] = b[t]*V, block-reduce
        float p[6];
#pragma unroll
        for (int t = 0; t < 6; ++t) p[t] = b[t] * V;
        warp_reduce6(p);
        if (lane == 0)
#pragma unroll
            for (int t = 0; t < 6; ++t) wpart[wid][t] = p[t];
        __syncthreads();
        if (wid == 0) {
            float q[6];
#pragma unroll
            for (int t = 0; t < 6; ++t) q[t] = (lane < NWARPS) ? wpart[lane][t] : 0.f;
            warp_reduce6(q);
            // collapse to ONE weighted scalar and multicast to all 8 CTAs
            float wsum = 0.f;
#pragma unroll
            for (int t = 0; t < 6; ++t) wsum = fmaf(c1[t], q[t], wsum);
            if (lane < CLUSTERS)
                dsmem_st(smem_u32(&slot[par][rank]), lane, wsum);
        }
        asm volatile("barrier.cluster.arrive.aligned;" ::: "memory");

        // ---- HH gate math (independent of Isyn) — EXACT R3 forms ----
        float v  = V;
        float e1 = __expf(1.0f - 0.1f * v);
        float e2 = __expf(-v * (1.0f / 18.0f));
        float e3 = __expf(-v * 0.05f);
        float e4 = __expf(-v * 0.0125f);
        float am = __fdividef(2.5f - 0.1f * v, fmaf(4.481689070338065f, e1, -1.0f));
        float bm = 4.0f * e2;
        float ah = 0.07f * e3;
        float bh = __fdividef(1.0f, fmaf(7.38905609893065f, e1, 1.0f));
        float an = __fdividef(0.1f - 0.01f * v, e1 - 1.0f);
        float bn = 0.125f * e4;
        mM = mM + DTc * (am * (1.0f - mM) - bm * mM);
        hH = hH + DTc * (ah * (1.0f - hH) - bh * hH);
        nN = nN + DTc * (an * (1.0f - nN) - bn * nN);
        float INa = 120.0f * mM * mM * mM * hH * (v - 50.0f);
        float n2  = nN * nN;
        float IK  = 36.0f * n2 * n2 * (v + 77.0f);
        float IL  = 0.3f * (v + 54.387f);
        float hhcur = INa + IK + IL;

        asm volatile("barrier.cluster.wait.aligned;" ::: "memory");

        // Isyn = sum of 8 weighted scalars + G-term recurrence
        float Is = u1 + u2;
#pragma unroll
        for (int r = 0; r < CLUSTERS; ++r) Is += slot[par][r];

        float vn = v + DTc * (Ie + Is - hhcur);
        // jnp semantics: clip(+-inf)->+-100; NaN->0 (fast-math-proof bit test)
        unsigned u = __float_as_uint(vn) & 0x7fffffffu;
        if (u > 0x7f800000u) vn = 0.0f;
        else                 vn = fminf(fmaxf(vn, -100.0f), 100.0f);
        V = vn;
        out[(size_t)k * Nn + j] = vn;
    }
}

// ---------------------------------------------------------------------------
extern "C" void kernel_launch(void* const* d_in, const int* in_sizes, int n_in,
                              void* d_out, int out_size) {
    const float* I_ext = (const float*)d_in[0];
    const float* W     = (const float*)d_in[1];
    const float* V0    = (const float*)d_in[2];
    const float* m0    = (const float*)d_in[3];
    const float* h0    = (const float*)d_in[4];
    const float* n0    = (const float*)d_in[5];
    const float* s0    = (const float*)d_in[6];
    const int*   Ty    = (const int*)d_in[7];
    float* out = (float*)d_out;

    const int steps = out_size / Nn;   // 1000

    dim3 g1(Nn / 4 / 256, ROWCHUNKS);
    k_cols_partial<<<g1, 256>>>((const float4*)W, (const int4*)Ty);
    k_build_b<<<(6 * Nn + 255) / 256, 256>>>(s0);
    k_hh<<<CLUSTERS, CTHREADS>>>(I_ext, V0, m0, h0, n0, out, steps);
}

// round 6
// speedup vs baseline: 4.4143x; 2.0518x over previous
#include <cuda_runtime.h>
#include <cuda_bf16.h>
#include <cstdint>

// HH neuron network, N=4096, 1000 steps.
// s has no V-feedback -> O(N^2) collapses to per-step weighted dot vs
// b[t][j]=s0*cols. R6: 8-SM cluster; per-step all-reduce of ONE pre-weighted
// scalar per CTA via st.async + mbarrier (no cluster barrier on the hot path).
// Per-neuron gate math identical to R3/R4 (NaN onset must match reference).

#define Nn        4096
#define CLUSTERS  8
#define CTHREADS  512
#define NWARPS    (CTHREADS/32)
#define ROWCHUNKS 64
#define DTc       0.01f

__device__ float g_part[(size_t)ROWCHUNKS * 6 * Nn];
__device__ float g_b[6 * Nn];

// ---------------------------------------------------------------------------
// Setup 1: partial per-type masked column sums of W (scalar R3 version: best
// measured — 25.8us, 67.9% DRAM; float4 variant tanked occupancy).
// ---------------------------------------------------------------------------
__global__ void k_cols_partial(const float* __restrict__ W,
                               const int*   __restrict__ Ty) {
    const int j  = blockIdx.x * blockDim.x + threadIdx.x;
    const int r0 = blockIdx.y * (Nn / ROWCHUNKS);
    float s0_ = 0.f, s1_ = 0.f, s2_ = 0.f, s3_ = 0.f, s4_ = 0.f, s5_ = 0.f;
#pragma unroll 2
    for (int r = r0; r < r0 + Nn / ROWCHUNKS; ++r) {
        size_t idx = (size_t)r * Nn + j;
        float w = W[idx];
        int   t = Ty[idx];
        s0_ += (t == 1) ? w : 0.f;
        s1_ += (t == 2) ? w : 0.f;
        s2_ += (t == 3) ? w : 0.f;
        s3_ += (t == 4) ? w : 0.f;
        s4_ += (t == 5) ? w : 0.f;
        s5_ += (t == 6) ? w : 0.f;
    }
    float* base = g_part + (size_t)blockIdx.y * 6 * Nn;
    base[0 * Nn + j] = s0_;
    base[1 * Nn + j] = s1_;
    base[2 * Nn + j] = s2_;
    base[3 * Nn + j] = s3_;
    base[4 * Nn + j] = s4_;
    base[5 * Nn + j] = s5_;
}

// ---------------------------------------------------------------------------
// Setup 2: b[t][j] = (sum of partials) * s0[t][j]
// ---------------------------------------------------------------------------
__global__ void k_build_b(const float* __restrict__ s0) {
    int idx = blockIdx.x * blockDim.x + threadIdx.x;
    if (idx >= 6 * Nn) return;
    float acc = 0.f;
#pragma unroll 8
    for (int c = 0; c < ROWCHUNKS; ++c)
        acc += g_part[(size_t)c * 6 * Nn + idx];
    g_b[idx] = acc * s0[idx];
}

// ---------------------------------------------------------------------------
__device__ __forceinline__ void warp_reduce6(float* p) {
#pragma unroll
    for (int o = 16; o > 0; o >>= 1) {
#pragma unroll
        for (int t = 0; t < 6; ++t)
            p[t] += __shfl_xor_sync(0xffffffffu, p[t], o);
    }
}

__device__ __forceinline__ uint32_t smem_u32(const void* p) {
    return (uint32_t)__cvta_generic_to_shared(p);
}
__device__ __forceinline__ void dsmem_st(uint32_t laddr, unsigned rank, float v) {
    uint32_t r;
    asm volatile("mapa.shared::cluster.u32 %0, %1, %2;" : "=r"(r) : "r"(laddr), "r"(rank));
    asm volatile("st.shared::cluster.f32 [%0], %1;" :: "r"(r), "f"(v) : "memory");
}
// st.async: remote store whose completion signals the REMOTE CTA's mbarrier.
__device__ __forceinline__ void dsmem_st_async(uint32_t lslot, uint32_t lmbar,
                                               unsigned rank, float v) {
    uint32_t rs, rm;
    asm volatile("mapa.shared::cluster.u32 %0, %1, %2;" : "=r"(rs) : "r"(lslot), "r"(rank));
    asm volatile("mapa.shared::cluster.u32 %0, %1, %2;" : "=r"(rm) : "r"(lmbar), "r"(rank));
    asm volatile("st.async.shared::cluster.mbarrier::complete_tx::bytes.f32 [%0], %1, [%2];"
                 :: "r"(rs), "f"(v), "r"(rm) : "memory");
}
__device__ __forceinline__ void mbar_init(uint32_t a, uint32_t cnt) {
    asm volatile("mbarrier.init.shared.b64 [%0], %1;" :: "r"(a), "r"(cnt) : "memory");
}
__device__ __forceinline__ void mbar_expect_tx(uint32_t a, uint32_t bytes) {
    asm volatile("mbarrier.arrive.expect_tx.shared.b64 _, [%0], %1;"
                 :: "r"(a), "r"(bytes) : "memory");
}
__device__ __forceinline__ void mbar_wait_parity(uint32_t a, uint32_t parity) {
    uint32_t done = 0;
    while (!done) {
        asm volatile(
            "{\n\t.reg .pred p;\n\t"
            "mbarrier.try_wait.parity.acquire.cta.shared::cta.b64 p, [%1], %2, 0x989680;\n\t"
            "selp.b32 %0, 1, 0, p;\n\t}"
            : "=r"(done) : "r"(a), "r"(parity) : "memory");
    }
}

// ---------------------------------------------------------------------------
// Cluster-of-8 persistent time stepper. 1 neuron/thread.
// ---------------------------------------------------------------------------
__global__ __cluster_dims__(CLUSTERS, 1, 1) __launch_bounds__(CTHREADS, 1)
void k_hh(const float* __restrict__ Iext_g, const float* __restrict__ V0,
          const float* __restrict__ m0,     const float* __restrict__ h0,
          const float* __restrict__ n0,     float* __restrict__ out, int steps) {
    __shared__ float wpart[NWARPS];
    __shared__ float slot[2][8];                    // [step parity][source rank]
    __shared__ __align__(8) unsigned long long mbar[2];
    __shared__ float Bslot[8][8];                   // one-time B exchange

    const int tid  = threadIdx.x;
    const int lane = tid & 31;
    const int wid  = tid >> 5;
    unsigned rank;
    asm("mov.u32 %0, %%cluster_ctarank;" : "=r"(rank));
    const int j = (int)rank * CTHREADS + tid;       // my neuron

    // per-thread state
    float b[6];
#pragma unroll
    for (int t = 0; t < 6; ++t) b[t] = g_b[t * Nn + j];
    float V  = V0[j], mM = m0[j], hH = h0[j], nN = n0[j], Ie = Iext_g[j];

    const float DEC[6] = {1.0f - 0.01f / 2.0f,   1.0f - 0.01f / 5.0f,
                          1.0f - 0.01f / 10.0f,  1.0f - 0.01f / 100.0f,
                          1.0f - 0.01f / 50.0f,  1.0f - 0.01f / 30.0f};
    const float SGN[6] = {-1.f, 1.f, 1.f, -1.f, -1.f, -1.f};

    if (tid == 0) { mbar_init(smem_u32(&mbar[0]), 1); mbar_init(smem_u32(&mbar[1]), 1); }

    // ---- one-time: B[t] partials exchanged via plain DSMEM + cluster barrier
    {
        float p[6];
#pragma unroll
        for (int t = 0; t < 6; ++t) p[t] = b[t];
        warp_reduce6(p);
        __shared__ float bp6[NWARPS][8];
        if (lane == 0)
#pragma unroll
            for (int t = 0; t < 6; ++t) bp6[wid][t] = p[t];
        __syncthreads();
        if (wid == 0) {
            float q[6];
#pragma unroll
            for (int t = 0; t < 6; ++t) q[t] = (lane < NWARPS) ? bp6[lane][t] : 0.f;
            warp_reduce6(q);
            if (lane < CLUSTERS)
#pragma unroll
                for (int t = 0; t < 6; ++t)
                    dsmem_st(smem_u32(&Bslot[rank][t]), lane, q[t]);
        }
        asm volatile("barrier.cluster.arrive.aligned;" ::: "memory");
        asm volatile("barrier.cluster.wait.aligned;"   ::: "memory");
    }
    float B1 = 0.f, B2 = 0.f;
#pragma unroll
    for (int r = 0; r < CLUSTERS; ++r) { B1 += Bslot[r][1]; B2 += Bslot[r][2]; }

    // per-thread recurrences: c1[t] = SGN*0.1*DEC^(k+1); u terms fold E_SYN*B
    float u1 = 7.0f * B1;                 // +0.1*70*dk1*B1
    float u2 = 9.0f * B2;                 // +0.1*90*dk2*B2
    float c1[6];
#pragma unroll
    for (int t = 0; t < 6; ++t) c1[t] = SGN[t] * 0.1f;

    const uint32_t slot_a[2] = { smem_u32(&slot[0][0]), smem_u32(&slot[1][0]) };
    const uint32_t mbar_a[2] = { smem_u32(&mbar[0]),    smem_u32(&mbar[1])    };

    for (int k = 0; k < steps; ++k) {
        const int      par    = k & 1;
        const uint32_t parity = (uint32_t)((k >> 1) & 1);

        if (tid == 0) mbar_expect_tx(mbar_a[par], 8 * 4);

        // decay update (dk = DEC^(k+1): ref applies s *= decay BEFORE use)
#pragma unroll
        for (int t = 0; t < 6; ++t) c1[t] *= DEC[t];
        u1 *= DEC[1];
        u2 *= DEC[2];

        // pre-weighted scalar: w = V * sum_t c1[t]*b[t]
        float acc = c1[0] * b[0];
#pragma unroll
        for (int t = 1; t < 6; ++t) acc = fmaf(c1[t], b[t], acc);
        float w = acc * V;
#pragma unroll
        for (int o = 16; o > 0; o >>= 1)
            w += __shfl_xor_sync(0xffffffffu, w, o);
        if (lane == 0) wpart[wid] = w;
        __syncthreads();
        if (wid == 0) {
            float q = (lane < NWARPS) ? wpart[lane] : 0.f;
#pragma unroll
            for (int o = 8; o > 0; o >>= 1)
                q += __shfl_xor_sync(0xffffffffu, q, o);
            if (lane < CLUSTERS)
                dsmem_st_async(slot_a[par] + 4u * rank, mbar_a[par], lane, q);
        }

        // ---- HH gate math (independent of Isyn) — EXACT R3 forms ----
        float v  = V;
        float e1 = __expf(1.0f - 0.1f * v);
        float e2 = __expf(-v * (1.0f / 18.0f));
        float e3 = __expf(-v * 0.05f);
        float e4 = __expf(-v * 0.0125f);
        float am = __fdividef(2.5f - 0.1f * v, fmaf(4.481689070338065f, e1, -1.0f));
        float bm = 4.0f * e2;
        float ah = 0.07f * e3;
        float bh = __fdividef(1.0f, fmaf(7.38905609893065f, e1, 1.0f));
        float an = __fdividef(0.1f - 0.01f * v, e1 - 1.0f);
        float bn = 0.125f * e4;
        mM = mM + DTc * (am * (1.0f - mM) - bm * mM);
        hH = hH + DTc * (ah * (1.0f - hH) - bh * hH);
        nN = nN + DTc * (an * (1.0f - nN) - bn * nN);
        float INa = 120.0f * mM * mM * mM * hH * (v - 50.0f);
        float n2  = nN * nN;
        float IK  = 36.0f * n2 * n2 * (v + 77.0f);
        float IL  = 0.3f * (v + 54.387f);
        float hhcur = INa + IK + IL;

        // wait for all 8 weighted scalars to land in my slots
        mbar_wait_parity(mbar_a[par], parity);

        float Is = u1 + u2;
        float4 s4a = *reinterpret_cast<const float4*>(&slot[par][0]);
        float4 s4b = *reinterpret_cast<const float4*>(&slot[par][4]);
        Is += s4a.x + s4a.y + s4a.z + s4a.w + s4b.x + s4b.y + s4b.z + s4b.w;

        float vn = v + DTc * (Ie + Is - hhcur);
        // jnp semantics: clip(+-inf)->+-100; NaN->0 (fast-math-proof bit test)
        unsigned u = __float_as_uint(vn) & 0x7fffffffu;
        if (u > 0x7f800000u) vn = 0.0f;
        else                 vn = fminf(fmaxf(vn, -100.0f), 100.0f);
        V = vn;
        out[(size_t)k * Nn + j] = vn;
    }

    // no CTA may exit while peers could still st.async into its SMEM
    asm volatile("barrier.cluster.arrive.aligned;" ::: "memory");
    asm volatile("barrier.cluster.wait.aligned;"   ::: "memory");
}

// ---------------------------------------------------------------------------
extern "C" void kernel_launch(void* const* d_in, const int* in_sizes, int n_in,
                              void* d_out, int out_size) {
    const float* I_ext = (const float*)d_in[0];
    const float* W     = (const float*)d_in[1];
    const float* V0    = (const float*)d_in[2];
    const float* m0    = (const float*)d_in[3];
    const float* h0    = (const float*)d_in[4];
    const float* n0    = (const float*)d_in[5];
    const float* s0    = (const float*)d_in[6];
    const int*   Ty    = (const int*)d_in[7];
    float* out = (float*)d_out;

    const int steps = out_size / Nn;   // 1000

    dim3 g1(Nn / 256, ROWCHUNKS);
    k_cols_partial<<<g1, 256>>>(W, Ty);
    k_build_b<<<(6 * Nn + 255) / 256, 256>>>(s0);
    k_hh<<<CLUSTERS, CTHREADS>>>(I_ext, V0, m0, h0, n0, out, steps);
}

// round 11
// speedup vs baseline: 12.7772x; 2.8945x over previous
#include <cuda_runtime.h>
#include <cuda_bf16.h>
#include <cstdint>

// HH neuron network, N=4096, 1000 steps.
// Key observations:
//  (1) s has no V-feedback -> O(N^2) collapses to per-step dots vs
//      b[t][j]=s0*cols (setup computes cols = masked column sums of W).
//  (2) V0/m0/h0/n0 are uniform and the per-neuron update is
//      V_j = clip(c + DT*Ie_j) with a SHARED scalar c whose magnitude is
//      ~1e4-1e6  -> every step every neuron saturates to the SAME value
//      (+-100, or 0 after NaN onset). So the whole simulation is a scalar
//      recurrence. A runtime guard verifies this; if it ever fails, a
//      full cluster fallback kernel (R6, known-correct) runs instead.

#define Nn        4096
#define CLUSTERS  8
#define CTHREADS  512
#define NWARPS    (CTHREADS/32)
#define ROWCHUNKS 64
#define DTc       0.01f

__device__ float g_part[(size_t)ROWCHUNKS * 6 * Nn];
__device__ float g_b[6 * Nn];
__device__ float g_rowval[4096];
__device__ int   g_ok;

// ---------------------------------------------------------------------------
// Setup 1: partial per-type masked column sums of W. Row loop unrolled x4.
// ---------------------------------------------------------------------------
__global__ void k_cols_partial(const float* __restrict__ W,
                               const int*   __restrict__ Ty) {
    const int j  = blockIdx.x * blockDim.x + threadIdx.x;
    const int r0 = blockIdx.y * (Nn / ROWCHUNKS);
    float acc[6] = {0.f, 0.f, 0.f, 0.f, 0.f, 0.f};
#pragma unroll 1
    for (int r = r0; r < r0 + Nn / ROWCHUNKS; r += 4) {
        size_t i0 = (size_t)r * Nn + j;
        float w0 = W[i0];           int t0 = Ty[i0];
        float w1 = W[i0 + Nn];      int t1 = Ty[i0 + Nn];
        float w2 = W[i0 + 2 * Nn];  int t2 = Ty[i0 + 2 * Nn];
        float w3 = W[i0 + 3 * Nn];  int t3 = Ty[i0 + 3 * Nn];
#pragma unroll
        for (int tt = 0; tt < 6; ++tt) {
            float a = acc[tt];
            a += (t0 == tt + 1) ? w0 : 0.f;
            a += (t1 == tt + 1) ? w1 : 0.f;
            a += (t2 == tt + 1) ? w2 : 0.f;
            a += (t3 == tt + 1) ? w3 : 0.f;
            acc[tt] = a;
        }
    }
    float* base = g_part + (size_t)blockIdx.y * 6 * Nn;
#pragma unroll
    for (int t = 0; t < 6; ++t) base[t * Nn + j] = acc[t];
}

// ---------------------------------------------------------------------------
// Setup 2: b[t][j] = (sum of partials) * s0[t][j]
// ---------------------------------------------------------------------------
__global__ void k_build_b(const float* __restrict__ s0) {
    int idx = blockIdx.x * blockDim.x + threadIdx.x;
    if (idx >= 6 * Nn) return;
    float acc = 0.f;
#pragma unroll 8
    for (int c = 0; c < ROWCHUNKS; ++c)
        acc += g_part[(size_t)c * 6 * Nn + idx];
    g_b[idx] = acc * s0[idx];
}

// ---------------------------------------------------------------------------
__device__ __forceinline__ void warp_reduce6(float* p) {
#pragma unroll
    for (int o = 16; o > 0; o >>= 1) {
#pragma unroll
        for (int t = 0; t < 6; ++t)
            p[t] += __shfl_xor_sync(0xffffffffu, p[t], o);
    }
}

// ---------------------------------------------------------------------------
// Scalar-path kernel: verify uniformity, compute B_t, run the scalar
// recurrence on thread 0, classify every step. Sets g_ok and g_rowval.
// ---------------------------------------------------------------------------
__global__ __launch_bounds__(512, 1)
void k_scalar(const float* __restrict__ Ie_g, const float* __restrict__ V0,
              const float* __restrict__ m0,   const float* __restrict__ h0,
              const float* __restrict__ n0,   int steps) {
    __shared__ float sB[16][8];
    __shared__ float sMax[16];
    __shared__ int   sBad;

    const int tid  = threadIdx.x;
    const int lane = tid & 31;
    const int wid  = tid >> 5;
    if (tid == 0) sBad = 0;
    __syncthreads();

    const float v0r = V0[0], m0r = m0[0], h0r = h0[0], n0r = n0[0];
    int   bad = 0;
    float mx  = 0.f;
    float p[6] = {0.f, 0.f, 0.f, 0.f, 0.f, 0.f};
    for (int j = tid; j < Nn; j += 512) {
        if (V0[j] != v0r || m0[j] != m0r || h0[j] != h0r || n0[j] != n0r) bad = 1;
        mx = fmaxf(mx, fabsf(Ie_g[j]));
#pragma unroll
        for (int t = 0; t < 6; ++t) p[t] += g_b[t * Nn + j];
    }
    warp_reduce6(p);
#pragma unroll
    for (int o = 16; o > 0; o >>= 1)
        mx = fmaxf(mx, __shfl_xor_sync(0xffffffffu, mx, o));
    bad = __any_sync(0xffffffffu, bad);
    if (lane == 0) {
#pragma unroll
        for (int t = 0; t < 6; ++t) sB[wid][t] = p[t];
        sMax[wid] = mx;
        if (bad) sBad = 1;
    }
    __syncthreads();
    if (tid != 0) return;

    if (sBad) { g_ok = 0; return; }

    float B[6];
#pragma unroll
    for (int t = 0; t < 6; ++t) {
        float a = 0.f;
#pragma unroll
        for (int w = 0; w < 16; ++w) a += sB[w][t];
        B[t] = a;
    }
    float mDtIe = 0.f;
#pragma unroll
    for (int w = 0; w < 16; ++w) mDtIe = fmaxf(mDtIe, sMax[w]);
    mDtIe *= DTc;

    const float DEC[6] = {1.0f - 0.01f / 2.0f,   1.0f - 0.01f / 5.0f,
                          1.0f - 0.01f / 10.0f,  1.0f - 0.01f / 100.0f,
                          1.0f - 0.01f / 50.0f,  1.0f - 0.01f / 30.0f};
    const float SGN[6] = {-1.f, 1.f, 1.f, -1.f, -1.f, -1.f};

    // Is(k) = V * sum_t a_t + (u1 + u2), with per-step decay of a_t, u1, u2.
    float a_t[6];
#pragma unroll
    for (int t = 0; t < 6; ++t) a_t[t] = SGN[t] * 0.1f * B[t];
    float u1 = 7.0f * B[1];      // 0.1 * 70 * B_GABAa  (E=-70, SGN=+1)
    float u2 = 9.0f * B[2];      // 0.1 * 90 * B_GABAb  (E=-90, SGN=+1)

    float V = v0r, mM = m0r, hH = h0r, nN = n0r;
    int ok = 1;

    for (int k = 0; k < steps; ++k) {
#pragma unroll
        for (int t = 0; t < 6; ++t) a_t[t] *= DEC[t];
        u1 *= DEC[1];
        u2 *= DEC[2];
        float asum = a_t[0] + a_t[1] + a_t[2] + a_t[3] + a_t[4] + a_t[5];
        float Is   = V * asum + u1 + u2;

        // ---- HH gate math — EXACT R3/R6 expression forms ----
        float v  = V;
        float e1 = __expf(1.0f - 0.1f * v);
        float e2 = __expf(-v * (1.0f / 18.0f));
        float e3 = __expf(-v * 0.05f);
        float e4 = __expf(-v * 0.0125f);
        float am = __fdividef(2.5f - 0.1f * v, fmaf(4.481689070338065f, e1, -1.0f));
        float bm = 4.0f * e2;
        float ah = 0.07f * e3;
        float bh = __fdividef(1.0f, fmaf(7.38905609893065f, e1, 1.0f));
        float an = __fdividef(0.1f - 0.01f * v, e1 - 1.0f);
        float bn = 0.125f * e4;
        mM = mM + DTc * (am * (1.0f - mM) - bm * mM);
        hH = hH + DTc * (ah * (1.0f - hH) - bh * hH);
        nN = nN + DTc * (an * (1.0f - nN) - bn * nN);
        float INa = 120.0f * mM * mM * mM * hH * (v - 50.0f);
        float n2  = nN * nN;
        float IK  = 36.0f * n2 * n2 * (v + 77.0f);
        float IL  = 0.3f * (v + 54.387f);
        float hhcur = INa + IK + IL;

        float c = v + DTc * (Is - hhcur);   // shared center; V_j = clip(c + DT*Ie_j)

        float row;
        unsigned ub = __float_as_uint(c) & 0x7fffffffu;
        if (ub > 0x7f800000u) {
            row = 0.0f;                      // NaN center -> all neurons NaN -> 0
        } else {
            // safety covers reassociation error (Is, hh) + per-neuron FP order
            float safety = fmaxf(2.0f, 1e-4f * fabsf(c));
            if (c >= 100.0f + mDtIe + safety)       row = 100.0f;
            else if (c <= -100.0f - mDtIe - safety) row = -100.0f;
            else { ok = 0; break; }          // non-uniform possible -> fallback
        }
        g_rowval[k] = row;
        V = row;
    }
    g_ok = ok;
}

// ---------------------------------------------------------------------------
// Broadcast writer (scalar path). One block per time step.
// ---------------------------------------------------------------------------
__global__ void k_write(float* __restrict__ out) {
    if (!g_ok) return;
    const int k = blockIdx.x;
    const float v = g_rowval[k];
    float4 f = make_float4(v, v, v, v);
    float4* row = reinterpret_cast<float4*>(out + (size_t)k * Nn);
    for (int i = threadIdx.x; i < Nn / 4; i += blockDim.x) row[i] = f;
}

// ---------------------------------------------------------------------------
// Fallback: R6 cluster kernel (known-correct, 510us). Early-exits if the
// scalar path succeeded.
// ---------------------------------------------------------------------------
__device__ __forceinline__ uint32_t smem_u32(const void* p) {
    return (uint32_t)__cvta_generic_to_shared(p);
}
__device__ __forceinline__ void dsmem_st(uint32_t laddr, unsigned rank, float v) {
    uint32_t r;
    asm volatile("mapa.shared::cluster.u32 %0, %1, %2;" : "=r"(r) : "r"(laddr), "r"(rank));
    asm volatile("st.shared::cluster.f32 [%0], %1;" :: "r"(r), "f"(v) : "memory");
}
__device__ __forceinline__ void dsmem_st_async(uint32_t lslot, uint32_t lmbar,
                                               unsigned rank, float v) {
    uint32_t rs, rm;
    asm volatile("mapa.shared::cluster.u32 %0, %1, %2;" : "=r"(rs) : "r"(lslot), "r"(rank));
    asm volatile("mapa.shared::cluster.u32 %0, %1, %2;" : "=r"(rm) : "r"(lmbar), "r"(rank));
    asm volatile("st.async.shared::cluster.mbarrier::complete_tx::bytes.f32 [%0], %1, [%2];"
                 :: "r"(rs), "f"(v), "r"(rm) : "memory");
}
__device__ __forceinline__ void mbar_init(uint32_t a, uint32_t cnt) {
    asm volatile("mbarrier.init.shared.b64 [%0], %1;" :: "r"(a), "r"(cnt) : "memory");
}
__device__ __forceinline__ void mbar_expect_tx(uint32_t a, uint32_t bytes) {
    asm volatile("mbarrier.arrive.expect_tx.shared.b64 _, [%0], %1;"
                 :: "r"(a), "r"(bytes) : "memory");
}
__device__ __forceinline__ void mbar_wait_parity(uint32_t a, uint32_t parity) {
    uint32_t done = 0;
    while (!done) {
        asm volatile(
            "{\n\t.reg .pred p;\n\t"
            "mbarrier.try_wait.parity.acquire.cta.shared::cta.b64 p, [%1], %2, 0x989680;\n\t"
            "selp.b32 %0, 1, 0, p;\n\t}"
            : "=r"(done) : "r"(a), "r"(parity) : "memory");
    }
}

__global__ __cluster_dims__(CLUSTERS, 1, 1) __launch_bounds__(CTHREADS, 1)
void k_hh(const float* __restrict__ Iext_g, const float* __restrict__ V0,
          const float* __restrict__ m0,     const float* __restrict__ h0,
          const float* __restrict__ n0,     float* __restrict__ out, int steps) {
    if (*(volatile int*)&g_ok) return;     // scalar path already wrote output

    __shared__ float wpart[NWARPS];
    __shared__ float slot[2][8];
    __shared__ __align__(8) unsigned long long mbar[2];
    __shared__ float Bslot[8][8];

    const int tid  = threadIdx.x;
    const int lane = tid & 31;
    const int wid  = tid >> 5;
    unsigned rank;
    asm("mov.u32 %0, %%cluster_ctarank;" : "=r"(rank));
    const int j = (int)rank * CTHREADS + tid;

    float b[6];
#pragma unroll
    for (int t = 0; t < 6; ++t) b[t] = g_b[t * Nn + j];
    float V  = V0[j], mM = m0[j], hH = h0[j], nN = n0[j], Ie = Iext_g[j];

    const float DEC[6] = {1.0f - 0.01f / 2.0f,   1.0f - 0.01f / 5.0f,
                          1.0f - 0.01f / 10.0f,  1.0f - 0.01f / 100.0f,
                          1.0f - 0.01f / 50.0f,  1.0f - 0.01f / 30.0f};
    const float SGN[6] = {-1.f, 1.f, 1.f, -1.f, -1.f, -1.f};

    if (tid == 0) { mbar_init(smem_u32(&mbar[0]), 1); mbar_init(smem_u32(&mbar[1]), 1); }

    {
        float p[6];
#pragma unroll
        for (int t = 0; t < 6; ++t) p[t] = b[t];
        warp_reduce6(p);
        __shared__ float bp6[NWARPS][8];
        if (lane == 0)
#pragma unroll
            for (int t = 0; t < 6; ++t) bp6[wid][t] = p[t];
        __syncthreads();
        if (wid == 0) {
            float q[6];
#pragma unroll
            for (int t = 0; t < 6; ++t) q[t] = (lane < NWARPS) ? bp6[lane][t] : 0.f;
            warp_reduce6(q);
            if (lane < CLUSTERS)
#pragma unroll
                for (int t = 0; t < 6; ++t)
                    dsmem_st(smem_u32(&Bslot[rank][t]), lane, q[t]);
        }
        asm volatile("barrier.cluster.arrive.aligned;" ::: "memory");
        asm volatile("barrier.cluster.wait.aligned;"   ::: "memory");
    }
    float B1 = 0.f, B2 = 0.f;
#pragma unroll
    for (int r = 0; r < CLUSTERS; ++r) { B1 += Bslot[r][1]; B2 += Bslot[r][2]; }

    float u1 = 7.0f * B1;
    float u2 = 9.0f * B2;
    float c1[6];
#pragma unroll
    for (int t = 0; t < 6; ++t) c1[t] = SGN[t] * 0.1f;

    const uint32_t slot_a[2] = { smem_u32(&slot[0][0]), smem_u32(&slot[1][0]) };
    const uint32_t mbar_a[2] = { smem_u32(&mbar[0]),    smem_u32(&mbar[1])    };

    for (int k = 0; k < steps; ++k) {
        const int      par    = k & 1;
        const uint32_t parity = (uint32_t)((k >> 1) & 1);

        if (tid == 0) mbar_expect_tx(mbar_a[par], 8 * 4);

#pragma unroll
        for (int t = 0; t < 6; ++t) c1[t] *= DEC[t];
        u1 *= DEC[1];
        u2 *= DEC[2];

        float acc = c1[0] * b[0];
#pragma unroll
        for (int t = 1; t < 6; ++t) acc = fmaf(c1[t], b[t], acc);
        float w = acc * V;
#pragma unroll
        for (int o = 16; o > 0; o >>= 1)
            w += __shfl_xor_sync(0xffffffffu, w, o);
        if (lane == 0) wpart[wid] = w;
        __syncthreads();
        if (wid == 0) {
            float q = (lane < NWARPS) ? wpart[lane] : 0.f;
#pragma unroll
            for (int o = 8; o > 0; o >>= 1)
                q += __shfl_xor_sync(0xffffffffu, q, o);
            if (lane < CLUSTERS)
                dsmem_st_async(slot_a[par] + 4u * rank, mbar_a[par], lane, q);
        }

        float v  = V;
        float e1 = __expf(1.0f - 0.1f * v);
        float e2 = __expf(-v * (1.0f / 18.0f));
        float e3 = __expf(-v * 0.05f);
        float e4 = __expf(-v * 0.0125f);
        float am = __fdividef(2.5f - 0.1f * v, fmaf(4.481689070338065f, e1, -1.0f));
        float bm = 4.0f * e2;
        float ah = 0.07f * e3;
        float bh = __fdividef(1.0f, fmaf(7.38905609893065f, e1, 1.0f));
        float an = __fdividef(0.1f - 0.01f * v, e1 - 1.0f);
        float bn = 0.125f * e4;
        mM = mM + DTc * (am * (1.0f - mM) - bm * mM);
        hH = hH + DTc * (ah * (1.0f - hH) - bh * hH);
        nN = nN + DTc * (an * (1.0f - nN) - bn * nN);
        float INa = 120.0f * mM * mM * mM * hH * (v - 50.0f);
        float n2  = nN * nN;
        float IK  = 36.0f * n2 * n2 * (v + 77.0f);
        float IL  = 0.3f * (v + 54.387f);
        float hhcur = INa + IK + IL;

        mbar_wait_parity(mbar_a[par], parity);

        float Is = u1 + u2;
        float4 s4a = *reinterpret_cast<const float4*>(&slot[par][0]);
        float4 s4b = *reinterpret_cast<const float4*>(&slot[par][4]);
        Is += s4a.x + s4a.y + s4a.z + s4a.w + s4b.x + s4b.y + s4b.z + s4b.w;

        float vn = v + DTc * (Ie + Is - hhcur);
        unsigned u = __float_as_uint(vn) & 0x7fffffffu;
        if (u > 0x7f800000u) vn = 0.0f;
        else                 vn = fminf(fmaxf(vn, -100.0f), 100.0f);
        V = vn;
        out[(size_t)k * Nn + j] = vn;
    }

    asm volatile("barrier.cluster.arrive.aligned;" ::: "memory");
    asm volatile("barrier.cluster.wait.aligned;"   ::: "memory");
}

// ---------------------------------------------------------------------------
extern "C" void kernel_launch(void* const* d_in, const int* in_sizes, int n_in,
                              void* d_out, int out_size) {
    const float* I_ext = (const float*)d_in[0];
    const float* W     = (const float*)d_in[1];
    const float* V0    = (const float*)d_in[2];
    const float* m0    = (const float*)d_in[3];
    const float* h0    = (const float*)d_in[4];
    const float* n0    = (const float*)d_in[5];
    const float* s0    = (const float*)d_in[6];
    const int*   Ty    = (const int*)d_in[7];
    float* out = (float*)d_out;

    const int steps = out_size / Nn;   // 1000

    dim3 g1(Nn / 256, ROWCHUNKS);
    k_cols_partial<<<g1, 256>>>(W, Ty);
    k_build_b<<<(6 * Nn + 255) / 256, 256>>>(s0);
    k_scalar<<<1, 512>>>(I_ext, V0, m0, h0, n0, steps);
    k_write<<<steps, 256>>>(out);
    k_hh<<<CLUSTERS, CTHREADS>>>(I_ext, V0, m0, h0, n0, out, steps);
}

// round 12
// speedup vs baseline: 32.1297x; 2.5146x over previous
#include <cuda_runtime.h>
#include <cuda_bf16.h>
#include <cstdint>

// HH neuron network, N=4096, 1000 steps.
//  (1) s has no V-feedback -> O(N^2) collapses to per-step dots vs
//      b[t][j]=s0*cols.
//  (2) V0/m0/h0/n0 uniform and |shared center c| ~ 1e4-1e6 -> every neuron
//      saturates to the SAME value each step (scalar recurrence). Runtime
//      guard verifies; fallback = known-correct R6 cluster kernel.
//  (3) R12: once m-gate is NaN and row==0, the state is a FIXED POINT
//      (NaN propagates; c=NaN; row=0 forever) -> break the serial loop at
//      NaN onset (~step 30-60) instead of running 1000 steps.

#define Nn        4096
#define CLUSTERS  8
#define CTHREADS  512
#define NWARPS    (CTHREADS/32)
#define ROWCHUNKS 64
#define DTc       0.01f

__device__ float g_part[(size_t)ROWCHUNKS * 6 * Nn];
__device__ float g_b[6 * Nn];
__device__ float g_rowval[4096];
__device__ int   g_onset;       // rows >= g_onset are all g_tail
__device__ float g_tail;
__device__ int   g_ok;

__device__ __forceinline__ bool is_nan_bits(float x) {
    return (__float_as_uint(x) & 0x7fffffffu) > 0x7f800000u;
}

// ---------------------------------------------------------------------------
// Setup 1: partial per-type masked column sums of W. Rows unrolled x8 (MLP).
// ---------------------------------------------------------------------------
__global__ void k_cols_partial(const float* __restrict__ W,
                               const int*   __restrict__ Ty) {
    const int j  = blockIdx.x * blockDim.x + threadIdx.x;
    const int r0 = blockIdx.y * (Nn / ROWCHUNKS);
    float acc[6] = {0.f, 0.f, 0.f, 0.f, 0.f, 0.f};
#pragma unroll 1
    for (int r = r0; r < r0 + Nn / ROWCHUNKS; r += 8) {
        float w[8];
        int   t[8];
        size_t i0 = (size_t)r * Nn + j;
#pragma unroll
        for (int u = 0; u < 8; ++u) {
            w[u] = W[i0 + (size_t)u * Nn];
            t[u] = Ty[i0 + (size_t)u * Nn];
        }
#pragma unroll
        for (int tt = 0; tt < 6; ++tt) {
            float a = acc[tt];
#pragma unroll
            for (int u = 0; u < 8; ++u)
                a += (t[u] == tt + 1) ? w[u] : 0.f;
            acc[tt] = a;
        }
    }
    float* base = g_part + (size_t)blockIdx.y * 6 * Nn;
#pragma unroll
    for (int t = 0; t < 6; ++t) base[t * Nn + j] = acc[t];
}

// ---------------------------------------------------------------------------
// Setup 2: b[t][j] = (sum of partials) * s0[t][j]
// ---------------------------------------------------------------------------
__global__ void k_build_b(const float* __restrict__ s0) {
    int idx = blockIdx.x * blockDim.x + threadIdx.x;
    if (idx >= 6 * Nn) return;
    float acc = 0.f;
#pragma unroll 8
    for (int c = 0; c < ROWCHUNKS; ++c)
        acc += g_part[(size_t)c * 6 * Nn + idx];
    g_b[idx] = acc * s0[idx];
}

// ---------------------------------------------------------------------------
__device__ __forceinline__ void warp_reduce6(float* p) {
#pragma unroll
    for (int o = 16; o > 0; o >>= 1) {
#pragma unroll
        for (int t = 0; t < 6; ++t)
            p[t] += __shfl_xor_sync(0xffffffffu, p[t], o);
    }
}

// ---------------------------------------------------------------------------
// Scalar-path kernel with NaN-fixed-point early break.
// ---------------------------------------------------------------------------
__global__ __launch_bounds__(512, 1)
void k_scalar(const float* __restrict__ Ie_g, const float* __restrict__ V0,
              const float* __restrict__ m0,   const float* __restrict__ h0,
              const float* __restrict__ n0,   int steps) {
    __shared__ float sB[16][8];
    __shared__ float sMax[16];
    __shared__ int   sBad;

    const int tid  = threadIdx.x;
    const int lane = tid & 31;
    const int wid  = tid >> 5;
    if (tid == 0) sBad = 0;
    __syncthreads();

    const float v0r = V0[0], m0r = m0[0], h0r = h0[0], n0r = n0[0];
    int   bad = 0;
    float mx  = 0.f;
    float p[6] = {0.f, 0.f, 0.f, 0.f, 0.f, 0.f};
    for (int j = tid; j < Nn; j += 512) {
        if (V0[j] != v0r || m0[j] != m0r || h0[j] != h0r || n0[j] != n0r) bad = 1;
        mx = fmaxf(mx, fabsf(Ie_g[j]));
#pragma unroll
        for (int t = 0; t < 6; ++t) p[t] += g_b[t * Nn + j];
    }
    warp_reduce6(p);
#pragma unroll
    for (int o = 16; o > 0; o >>= 1)
        mx = fmaxf(mx, __shfl_xor_sync(0xffffffffu, mx, o));
    bad = __any_sync(0xffffffffu, bad);
    if (lane == 0) {
#pragma unroll
        for (int t = 0; t < 6; ++t) sB[wid][t] = p[t];
        sMax[wid] = mx;
        if (bad) sBad = 1;
    }
    __syncthreads();
    if (tid != 0) return;

    if (sBad) { g_ok = 0; return; }

    float B[6];
#pragma unroll
    for (int t = 0; t < 6; ++t) {
        float a = 0.f;
#pragma unroll
        for (int w = 0; w < 16; ++w) a += sB[w][t];
        B[t] = a;
    }
    float mDtIe = 0.f;
#pragma unroll
    for (int w = 0; w < 16; ++w) mDtIe = fmaxf(mDtIe, sMax[w]);
    mDtIe *= DTc;

    const float DEC[6] = {1.0f - 0.01f / 2.0f,   1.0f - 0.01f / 5.0f,
                          1.0f - 0.01f / 10.0f,  1.0f - 0.01f / 100.0f,
                          1.0f - 0.01f / 50.0f,  1.0f - 0.01f / 30.0f};
    const float SGN[6] = {-1.f, 1.f, 1.f, -1.f, -1.f, -1.f};

    float a_t[6];
#pragma unroll
    for (int t = 0; t < 6; ++t) a_t[t] = SGN[t] * 0.1f * B[t];
    float u1 = 7.0f * B[1];      // 0.1 * 70 * B_GABAa
    float u2 = 9.0f * B[2];      // 0.1 * 90 * B_GABAb

    float V = v0r, mM = m0r, hH = h0r, nN = n0r;
    int ok = 1;
    int onset = steps;

    for (int k = 0; k < steps; ++k) {
#pragma unroll
        for (int t = 0; t < 6; ++t) a_t[t] *= DEC[t];
        u1 *= DEC[1];
        u2 *= DEC[2];
        float asum = a_t[0] + a_t[1] + a_t[2] + a_t[3] + a_t[4] + a_t[5];
        float Is   = V * asum + u1 + u2;

        // ---- HH gate math — EXACT R3/R6 expression forms ----
        float v  = V;
        float e1 = __expf(1.0f - 0.1f * v);
        float e2 = __expf(-v * (1.0f / 18.0f));
        float e3 = __expf(-v * 0.05f);
        float e4 = __expf(-v * 0.0125f);
        float am = __fdividef(2.5f - 0.1f * v, fmaf(4.481689070338065f, e1, -1.0f));
        float bm = 4.0f * e2;
        float ah = 0.07f * e3;
        float bh = __fdividef(1.0f, fmaf(7.38905609893065f, e1, 1.0f));
        float an = __fdividef(0.1f - 0.01f * v, e1 - 1.0f);
        float bn = 0.125f * e4;
        mM = mM + DTc * (am * (1.0f - mM) - bm * mM);
        hH = hH + DTc * (ah * (1.0f - hH) - bh * hH);
        nN = nN + DTc * (an * (1.0f - nN) - bn * nN);
        float INa = 120.0f * mM * mM * mM * hH * (v - 50.0f);
        float n2  = nN * nN;
        float IK  = 36.0f * n2 * n2 * (v + 77.0f);
        float IL  = 0.3f * (v + 54.387f);
        float hhcur = INa + IK + IL;

        float c = v + DTc * (Is - hhcur);   // shared center; V_j = clip(c + DT*Ie_j)

        float row;
        if (is_nan_bits(c)) {
            row = 0.0f;                      // NaN center -> all neurons -> 0
        } else {
            float safety = fmaxf(2.0f, 1e-4f * fabsf(c));
            if (c >= 100.0f + mDtIe + safety)       row = 100.0f;
            else if (c <= -100.0f - mDtIe - safety) row = -100.0f;
            else { ok = 0; break; }          // ambiguous -> cluster fallback
        }
        g_rowval[k] = row;
        V = row;

        // FIXED POINT: mM NaN & row 0 -> hhcur NaN forever -> c NaN forever
        // -> all remaining rows are 0. (am,bm finite at v=0, NaN persists.)
        if (row == 0.0f && is_nan_bits(mM)) { onset = k + 1; break; }
    }
    g_onset = onset;
    g_tail  = 0.0f;
    g_ok    = ok;
}

// ---------------------------------------------------------------------------
// Broadcast writer (scalar path). 2 blocks per time step.
// ---------------------------------------------------------------------------
__global__ void k_write(float* __restrict__ out) {
    if (!g_ok) return;
    const int k    = blockIdx.x >> 1;
    const int half = blockIdx.x & 1;
    const float v  = (k < g_onset) ? g_rowval[k] : g_tail;
    float4 f = make_float4(v, v, v, v);
    float4* row = reinterpret_cast<float4*>(out + (size_t)k * Nn) + half * (Nn / 8);
    for (int i = threadIdx.x; i < Nn / 8; i += blockDim.x) row[i] = f;
}

// ---------------------------------------------------------------------------
// Fallback: R6 cluster kernel (known-correct). Early-exits if scalar path ok.
// ---------------------------------------------------------------------------
__device__ __forceinline__ uint32_t smem_u32(const void* p) {
    return (uint32_t)__cvta_generic_to_shared(p);
}
__device__ __forceinline__ void dsmem_st(uint32_t laddr, unsigned rank, float v) {
    uint32_t r;
    asm volatile("mapa.shared::cluster.u32 %0, %1, %2;" : "=r"(r) : "r"(laddr), "r"(rank));
    asm volatile("st.shared::cluster.f32 [%0], %1;" :: "r"(r), "f"(v) : "memory");
}
__device__ __forceinline__ void dsmem_st_async(uint32_t lslot, uint32_t lmbar,
                                               unsigned rank, float v) {
    uint32_t rs, rm;
    asm volatile("mapa.shared::cluster.u32 %0, %1, %2;" : "=r"(rs) : "r"(lslot), "r"(rank));
    asm volatile("mapa.shared::cluster.u32 %0, %1, %2;" : "=r"(rm) : "r"(lmbar), "r"(rank));
    asm volatile("st.async.shared::cluster.mbarrier::complete_tx::bytes.f32 [%0], %1, [%2];"
                 :: "r"(rs), "f"(v), "r"(rm) : "memory");
}
__device__ __forceinline__ void mbar_init(uint32_t a, uint32_t cnt) {
    asm volatile("mbarrier.init.shared.b64 [%0], %1;" :: "r"(a), "r"(cnt) : "memory");
}
__device__ __forceinline__ void mbar_expect_tx(uint32_t a, uint32_t bytes) {
    asm volatile("mbarrier.arrive.expect_tx.shared.b64 _, [%0], %1;"
                 :: "r"(a), "r"(bytes) : "memory");
}
__device__ __forceinline__ void mbar_wait_parity(uint32_t a, uint32_t parity) {
    uint32_t done = 0;
    while (!done) {
        asm volatile(
            "{\n\t.reg .pred p;\n\t"
            "mbarrier.try_wait.parity.acquire.cta.shared::cta.b64 p, [%1], %2, 0x989680;\n\t"
            "selp.b32 %0, 1, 0, p;\n\t}"
            : "=r"(done) : "r"(a), "r"(parity) : "memory");
    }
}

__global__ __cluster_dims__(CLUSTERS, 1, 1) __launch_bounds__(CTHREADS, 1)
void k_hh(const float* __restrict__ Iext_g, const float* __restrict__ V0,
          const float* __restrict__ m0,     const float* __restrict__ h0,
          const float* __restrict__ n0,     float* __restrict__ out, int steps) {
    if (*(volatile int*)&g_ok) return;

    __shared__ float wpart[NWARPS];
    __shared__ float slot[2][8];
    __shared__ __align__(8) unsigned long long mbar[2];
    __shared__ float Bslot[8][8];

    const int tid  = threadIdx.x;
    const int lane = tid & 31;
    const int wid  = tid >> 5;
    unsigned rank;
    asm("mov.u32 %0, %%cluster_ctarank;" : "=r"(rank));
    const int j = (int)rank * CTHREADS + tid;

    float b[6];
#pragma unroll
    for (int t = 0; t < 6; ++t) b[t] = g_b[t * Nn + j];
    float V  = V0[j], mM = m0[j], hH = h0[j], nN = n0[j], Ie = Iext_g[j];

    const float DEC[6] = {1.0f - 0.01f / 2.0f,   1.0f - 0.01f / 5.0f,
                          1.0f - 0.01f / 10.0f,  1.0f - 0.01f / 100.0f,
                          1.0f - 0.01f / 50.0f,  1.0f - 0.01f / 30.0f};
    const float SGN[6] = {-1.f, 1.f, 1.f, -1.f, -1.f, -1.f};

    if (tid == 0) { mbar_init(smem_u32(&mbar[0]), 1); mbar_init(smem_u32(&mbar[1]), 1); }

    {
        float p[6];
#pragma unroll
        for (int t = 0; t < 6; ++t) p[t] = b[t];
        warp_reduce6(p);
        __shared__ float bp6[NWARPS][8];
        if (lane == 0)
#pragma unroll
            for (int t = 0; t < 6; ++t) bp6[wid][t] = p[t];
        __syncthreads();
        if (wid == 0) {
            float q[6];
#pragma unroll
            for (int t = 0; t < 6; ++t) q[t] = (lane < NWARPS) ? bp6[lane][t] : 0.f;
            warp_reduce6(q);
            if (lane < CLUSTERS)
#pragma unroll
                for (int t = 0; t < 6; ++t)
                    dsmem_st(smem_u32(&Bslot[rank][t]), lane, q[t]);
        }
        asm volatile("barrier.cluster.arrive.aligned;" ::: "memory");
        asm volatile("barrier.cluster.wait.aligned;"   ::: "memory");
    }
    float B1 = 0.f, B2 = 0.f;
#pragma unroll
    for (int r = 0; r < CLUSTERS; ++r) { B1 += Bslot[r][1]; B2 += Bslot[r][2]; }

    float u1 = 7.0f * B1;
    float u2 = 9.0f * B2;
    float c1[6];
#pragma unroll
    for (int t = 0; t < 6; ++t) c1[t] = SGN[t] * 0.1f;

    const uint32_t slot_a[2] = { smem_u32(&slot[0][0]), smem_u32(&slot[1][0]) };
    const uint32_t mbar_a[2] = { smem_u32(&mbar[0]),    smem_u32(&mbar[1])    };

    for (int k = 0; k < steps; ++k) {
        const int      par    = k & 1;
        const uint32_t parity = (uint32_t)((k >> 1) & 1);

        if (tid == 0) mbar_expect_tx(mbar_a[par], 8 * 4);

#pragma unroll
        for (int t = 0; t < 6; ++t) c1[t] *= DEC[t];
        u1 *= DEC[1];
        u2 *= DEC[2];

        float acc = c1[0] * b[0];
#pragma unroll
        for (int t = 1; t < 6; ++t) acc = fmaf(c1[t], b[t], acc);
        float w = acc * V;
#pragma unroll
        for (int o = 16; o > 0; o >>= 1)
            w += __shfl_xor_sync(0xffffffffu, w, o);
        if (lane == 0) wpart[wid] = w;
        __syncthreads();
        if (wid == 0) {
            float q = (lane < NWARPS) ? wpart[lane] : 0.f;
#pragma unroll
            for (int o = 8; o > 0; o >>= 1)
                q += __shfl_xor_sync(0xffffffffu, q, o);
            if (lane < CLUSTERS)
                dsmem_st_async(slot_a[par] + 4u * rank, mbar_a[par], lane, q);
        }

        float v  = V;
        float e1 = __expf(1.0f - 0.1f * v);
        float e2 = __expf(-v * (1.0f / 18.0f));
        float e3 = __expf(-v * 0.05f);
        float e4 = __expf(-v * 0.0125f);
        float am = __fdividef(2.5f - 0.1f * v, fmaf(4.481689070338065f, e1, -1.0f));
        float bm = 4.0f * e2;
        float ah = 0.07f * e3;
        float bh = __fdividef(1.0f, fmaf(7.38905609893065f, e1, 1.0f));
        float an = __fdividef(0.1f - 0.01f * v, e1 - 1.0f);
        float bn = 0.125f * e4;
        mM = mM + DTc * (am * (1.0f - mM) - bm * mM);
        hH = hH + DTc * (ah * (1.0f - hH) - bh * hH);
        nN = nN + DTc * (an * (1.0f - nN) - bn * nN);
        float INa = 120.0f * mM * mM * mM * hH * (v - 50.0f);
        float n2  = nN * nN;
        float IK  = 36.0f * n2 * n2 * (v + 77.0f);
        float IL  = 0.3f * (v + 54.387f);
        float hhcur = INa + IK + IL;

        mbar_wait_parity(mbar_a[par], parity);

        float Is = u1 + u2;
        float4 s4a = *reinterpret_cast<const float4*>(&slot[par][0]);
        float4 s4b = *reinterpret_cast<const float4*>(&slot[par][4]);
        Is += s4a.x + s4a.y + s4a.z + s4a.w + s4b.x + s4b.y + s4b.z + s4b.w;

        float vn = v + DTc * (Ie + Is - hhcur);
        unsigned u = __float_as_uint(vn) & 0x7fffffffu;
        if (u > 0x7f800000u) vn = 0.0f;
        else                 vn = fminf(fmaxf(vn, -100.0f), 100.0f);
        V = vn;
        out[(size_t)k * Nn + j] = vn;
    }

    asm volatile("barrier.cluster.arrive.aligned;" ::: "memory");
    asm volatile("barrier.cluster.wait.aligned;"   ::: "memory");
}

// ---------------------------------------------------------------------------
extern "C" void kernel_launch(void* const* d_in, const int* in_sizes, int n_in,
                              void* d_out, int out_size) {
    const float* I_ext = (const float*)d_in[0];
    const float* W     = (const float*)d_in[1];
    const float* V0    = (const float*)d_in[2];
    const float* m0    = (const float*)d_in[3];
    const float* h0    = (const float*)d_in[4];
    const float* n0    = (const float*)d_in[5];
    const float* s0    = (const float*)d_in[6];
    const int*   Ty    = (const int*)d_in[7];
    float* out = (float*)d_out;

    const int steps = out_size / Nn;   // 1000

    dim3 g1(Nn / 256, ROWCHUNKS);
    k_cols_partial<<<g1, 256>>>(W, Ty);
    k_build_b<<<(6 * Nn + 255) / 256, 256>>>(s0);
    k_scalar<<<1, 512>>>(I_ext, V0, m0, h0, n0, steps);
    k_write<<<2 * steps, 128>>>(out);
    k_hh<<<CLUSTERS, CTHREADS>>>(I_ext, V0, m0, h0, n0, out, steps);
}

// round 15
// speedup vs baseline: 35.0593x; 1.0912x over previous
#include <cuda_runtime.h>
#include <cuda_bf16.h>
#include <cstdint>

// HH neuron network, N=4096, 1000 steps.
//  (1) s has no V-feedback -> O(N^2) collapses to per-step dots vs
//      b[t][j]=s0*cols.
//  (2) V0..n0 uniform & |shared center| ~1e5 -> scalar recurrence with
//      rail-valued V (guarded; fallback = R6 cluster kernel).
//  (3) NaN fixed point -> early break at onset (~step 100-140).
//  R13/R15: memoized rail rates (V in {100,-100,0} after step 1 -> select
//  precomputed gate rates instead of recomputing the MUFU chain);
//  build_b fused into k_scalar (last-block-takes-over); cols_partial
//  in the measured-best R3 form. (Resubmit: R14 was an infra failure.)

#define Nn        4096
#define CLUSTERS  8
#define CTHREADS  512
#define NWARPS    (CTHREADS/32)
#define ROWCHUNKS 64
#define BBLOCKS   64
#define DTc       0.01f

__device__ float g_part[(size_t)ROWCHUNKS * 6 * Nn];
__device__ float g_b[6 * Nn];
__device__ float g_rowval[4096];
__device__ int   g_onset;
__device__ float g_tail;
__device__ int   g_ok;
__device__ int   g_done = 0;       // last-block counter; reset each call

__device__ __forceinline__ bool is_nan_bits(float x) {
    return (__float_as_uint(x) & 0x7fffffffu) > 0x7f800000u;
}

// ---------------------------------------------------------------------------
// Setup 1: partial per-type masked column sums of W (R3 form: best measured).
// ---------------------------------------------------------------------------
__global__ void k_cols_partial(const float* __restrict__ W,
                               const int*   __restrict__ Ty) {
    const int j  = blockIdx.x * blockDim.x + threadIdx.x;
    const int r0 = blockIdx.y * (Nn / ROWCHUNKS);
    float s0_ = 0.f, s1_ = 0.f, s2_ = 0.f, s3_ = 0.f, s4_ = 0.f, s5_ = 0.f;
    for (int r = r0; r < r0 + Nn / ROWCHUNKS; ++r) {
        size_t idx = (size_t)r * Nn + j;
        float w = W[idx];
        int   t = Ty[idx];
        s0_ += (t == 1) ? w : 0.f;
        s1_ += (t == 2) ? w : 0.f;
        s2_ += (t == 3) ? w : 0.f;
        s3_ += (t == 4) ? w : 0.f;
        s4_ += (t == 5) ? w : 0.f;
        s5_ += (t == 6) ? w : 0.f;
    }
    float* base = g_part + (size_t)blockIdx.y * 6 * Nn;
    base[0 * Nn + j] = s0_;
    base[1 * Nn + j] = s1_;
    base[2 * Nn + j] = s2_;
    base[3 * Nn + j] = s3_;
    base[4 * Nn + j] = s4_;
    base[5 * Nn + j] = s5_;
}

// ---------------------------------------------------------------------------
__device__ __forceinline__ void warp_reduce6(float* p) {
#pragma unroll
    for (int o = 16; o > 0; o >>= 1) {
#pragma unroll
        for (int t = 0; t < 6; ++t)
            p[t] += __shfl_xor_sync(0xffffffffu, p[t], o);
    }
}

// gate rates at voltage v — EXACT R3/R6 expression forms
__device__ __forceinline__ void hh_rates(float v, float* r) {
    float e1 = __expf(1.0f - 0.1f * v);
    float e2 = __expf(-v * (1.0f / 18.0f));
    float e3 = __expf(-v * 0.05f);
    float e4 = __expf(-v * 0.0125f);
    r[0] = __fdividef(2.5f - 0.1f * v, fmaf(4.481689070338065f, e1, -1.0f)); // am
    r[1] = 4.0f * e2;                                                        // bm
    r[2] = 0.07f * e3;                                                       // ah
    r[3] = __fdividef(1.0f, fmaf(7.38905609893065f, e1, 1.0f));              // bh
    r[4] = __fdividef(0.1f - 0.01f * v, e1 - 1.0f);                          // an
    r[5] = 0.125f * e4;                                                      // bn
}

// ---------------------------------------------------------------------------
// Fused: build g_b (all 64 blocks) then last block verifies uniformity,
// reduces B[t], and runs the rail-memoized scalar recurrence.
// ---------------------------------------------------------------------------
__global__ __launch_bounds__(512, 1)
void k_scalar(const float* __restrict__ s0,   const float* __restrict__ Ie_g,
              const float* __restrict__ V0,   const float* __restrict__ m0,
              const float* __restrict__ h0,   const float* __restrict__ n0,
              int steps) {
    const int tid  = threadIdx.x;
    const int lane = tid & 31;
    const int wid  = tid >> 5;

    // ---- phase 1: my slice of b[t][j] = (sum of partials) * s0 ----
    const int per = 6 * Nn / BBLOCKS;                 // 384
    const int i0  = blockIdx.x * per;
    for (int i = i0 + tid; i < i0 + per; i += 512) {
        float acc = 0.f;
#pragma unroll 8
        for (int c = 0; c < ROWCHUNKS; ++c)
            acc += g_part[(size_t)c * 6 * Nn + i];
        g_b[i] = acc * s0[i];
    }

    // ---- last-block election (deterministic: g_b writes disjoint) ----
    __shared__ int sLast;
    __threadfence();
    __syncthreads();
    if (tid == 0) {
        int old = atomicAdd(&g_done, 1);
        sLast = (old == BBLOCKS - 1);
        if (sLast) g_done = 0;                        // reset for next replay
    }
    __syncthreads();
    if (!sLast) return;
    __threadfence();                                  // see all blocks' g_b

    // ---- phase 2 (last block only): scan + B reduce ----
    __shared__ float sB[16][8];
    __shared__ float sMax[16];
    __shared__ int   sBad;
    if (tid == 0) sBad = 0;
    __syncthreads();

    const float v0r = V0[0], m0r = m0[0], h0r = h0[0], n0r = n0[0];
    int   bad = 0;
    float mx  = 0.f;
    float p[6] = {0.f, 0.f, 0.f, 0.f, 0.f, 0.f};
    for (int j = tid; j < Nn; j += 512) {
        if (V0[j] != v0r || m0[j] != m0r || h0[j] != h0r || n0[j] != n0r) bad = 1;
        mx = fmaxf(mx, fabsf(Ie_g[j]));
#pragma unroll
        for (int t = 0; t < 6; ++t) p[t] += g_b[t * Nn + j];
    }
    warp_reduce6(p);
#pragma unroll
    for (int o = 16; o > 0; o >>= 1)
        mx = fmaxf(mx, __shfl_xor_sync(0xffffffffu, mx, o));
    bad = __any_sync(0xffffffffu, bad);
    if (lane == 0) {
#pragma unroll
        for (int t = 0; t < 6; ++t) sB[wid][t] = p[t];
        sMax[wid] = mx;
        if (bad) sBad = 1;
    }
    __syncthreads();
    if (tid != 0) return;

    if (sBad) { g_ok = 0; return; }

    float B[6];
#pragma unroll
    for (int t = 0; t < 6; ++t) {
        float a = 0.f;
#pragma unroll
        for (int w = 0; w < 16; ++w) a += sB[w][t];
        B[t] = a;
    }
    float mDtIe = 0.f;
#pragma unroll
    for (int w = 0; w < 16; ++w) mDtIe = fmaxf(mDtIe, sMax[w]);
    mDtIe *= DTc;

    const float DEC[6] = {1.0f - 0.01f / 2.0f,   1.0f - 0.01f / 5.0f,
                          1.0f - 0.01f / 10.0f,  1.0f - 0.01f / 100.0f,
                          1.0f - 0.01f / 50.0f,  1.0f - 0.01f / 30.0f};
    const float SGN[6] = {-1.f, 1.f, 1.f, -1.f, -1.f, -1.f};

    float a_t[6];
#pragma unroll
    for (int t = 0; t < 6; ++t) a_t[t] = SGN[t] * 0.1f * B[t];
    float u1 = 7.0f * B[1];
    float u2 = 9.0f * B[2];

    // memoized gate rates at the three rail values (same ops as inline path
    // -> bit-identical trajectory)
    float Rp[6], Rm[6], Rz[6];
    hh_rates( 100.0f, Rp);
    hh_rates(-100.0f, Rm);
    hh_rates(   0.0f, Rz);

    float V = v0r, mM = m0r, hH = h0r, nN = n0r;
    int ok = 1;
    int onset = steps;

    for (int k = 0; k < steps; ++k) {
#pragma unroll
        for (int t = 0; t < 6; ++t) a_t[t] *= DEC[t];
        u1 *= DEC[1];
        u2 *= DEC[2];
        float asum = a_t[0] + a_t[1] + a_t[2] + a_t[3] + a_t[4] + a_t[5];
        float Is   = V * asum + u1 + u2;

        float v = V;
        float r[6];
        if (v == 100.0f) {
#pragma unroll
            for (int t = 0; t < 6; ++t) r[t] = Rp[t];
        } else if (v == -100.0f) {
#pragma unroll
            for (int t = 0; t < 6; ++t) r[t] = Rm[t];
        } else if (v == 0.0f) {
#pragma unroll
            for (int t = 0; t < 6; ++t) r[t] = Rz[t];
        } else {
            hh_rates(v, r);                           // general (step 0)
        }
        mM = mM + DTc * (r[0] * (1.0f - mM) - r[1] * mM);
        hH = hH + DTc * (r[2] * (1.0f - hH) - r[3] * hH);
        nN = nN + DTc * (r[4] * (1.0f - nN) - r[5] * nN);
        float INa = 120.0f * mM * mM * mM * hH * (v - 50.0f);
        float n2  = nN * nN;
        float IK  = 36.0f * n2 * n2 * (v + 77.0f);
        float IL  = 0.3f * (v + 54.387f);
        float hhcur = INa + IK + IL;

        float c = v + DTc * (Is - hhcur);

        float row;
        if (is_nan_bits(c)) {
            row = 0.0f;
        } else {
            float safety = fmaxf(2.0f, 1e-4f * fabsf(c));
            if (c >= 100.0f + mDtIe + safety)       row = 100.0f;
            else if (c <= -100.0f - mDtIe - safety) row = -100.0f;
            else { ok = 0; break; }                   // ambiguous -> fallback
        }
        g_rowval[k] = row;
        V = row;

        // NaN fixed point: mM NaN & row 0 -> c NaN forever -> rows 0 forever
        if (row == 0.0f && is_nan_bits(mM)) { onset = k + 1; break; }
    }
    g_onset = onset;
    g_tail  = 0.0f;
    g_ok    = ok;
}

// ---------------------------------------------------------------------------
// Broadcast writer (scalar path). One block per time step.
// ---------------------------------------------------------------------------
__global__ void k_write(float* __restrict__ out) {
    if (!g_ok) return;
    const int k = blockIdx.x;
    const float v = (k < g_onset) ? g_rowval[k] : g_tail;
    float4 f = make_float4(v, v, v, v);
    float4* row = reinterpret_cast<float4*>(out + (size_t)k * Nn);
#pragma unroll
    for (int q = 0; q < 4; ++q)
        row[threadIdx.x + q * 256] = f;
}

// ---------------------------------------------------------------------------
// Fallback: R6 cluster kernel (known-correct). Early-exits if scalar path ok.
// ---------------------------------------------------------------------------
__device__ __forceinline__ uint32_t smem_u32(const void* p) {
    return (uint32_t)__cvta_generic_to_shared(p);
}
__device__ __forceinline__ void dsmem_st(uint32_t laddr, unsigned rank, float v) {
    uint32_t r;
    asm volatile("mapa.shared::cluster.u32 %0, %1, %2;" : "=r"(r) : "r"(laddr), "r"(rank));
    asm volatile("st.shared::cluster.f32 [%0], %1;" :: "r"(r), "f"(v) : "memory");
}
__device__ __forceinline__ void dsmem_st_async(uint32_t lslot, uint32_t lmbar,
                                               unsigned rank, float v) {
    uint32_t rs, rm;
    asm volatile("mapa.shared::cluster.u32 %0, %1, %2;" : "=r"(rs) : "r"(lslot), "r"(rank));
    asm volatile("mapa.shared::cluster.u32 %0, %1, %2;" : "=r"(rm) : "r"(lmbar), "r"(rank));
    asm volatile("st.async.shared::cluster.mbarrier::complete_tx::bytes.f32 [%0], %1, [%2];"
                 :: "r"(rs), "f"(v), "r"(rm) : "memory");
}
__device__ __forceinline__ void mbar_init(uint32_t a, uint32_t cnt) {
    asm volatile("mbarrier.init.shared.b64 [%0], %1;" :: "r"(a), "r"(cnt) : "memory");
}
__device__ __forceinline__ void mbar_expect_tx(uint32_t a, uint32_t bytes) {
    asm volatile("mbarrier.arrive.expect_tx.shared.b64 _, [%0], %1;"
                 :: "r"(a), "r"(bytes) : "memory");
}
__device__ __forceinline__ void mbar_wait_parity(uint32_t a, uint32_t parity) {
    uint32_t done = 0;
    while (!done) {
        asm volatile(
            "{\n\t.reg .pred p;\n\t"
            "mbarrier.try_wait.parity.acquire.cta.shared::cta.b64 p, [%1], %2, 0x989680;\n\t"
            "selp.b32 %0, 1, 0, p;\n\t}"
            : "=r"(done) : "r"(a), "r"(parity) : "memory");
    }
}

__global__ __cluster_dims__(CLUSTERS, 1, 1) __launch_bounds__(CTHREADS, 1)
void k_hh(const float* __restrict__ Iext_g, const float* __restrict__ V0,
          const float* __restrict__ m0,     const float* __restrict__ h0,
          const float* __restrict__ n0,     float* __restrict__ out, int steps) {
    if (*(volatile int*)&g_ok) return;

    __shared__ float wpart[NWARPS];
    __shared__ float slot[2][8];
    __shared__ __align__(8) unsigned long long mbar[2];
    __shared__ float Bslot[8][8];

    const int tid  = threadIdx.x;
    const int lane = tid & 31;
    const int wid  = tid >> 5;
    unsigned rank;
    asm("mov.u32 %0, %%cluster_ctarank;" : "=r"(rank));
    const int j = (int)rank * CTHREADS + tid;

    float b[6];
#pragma unroll
    for (int t = 0; t < 6; ++t) b[t] = g_b[t * Nn + j];
    float V  = V0[j], mM = m0[j], hH = h0[j], nN = n0[j], Ie = Iext_g[j];

    const float DEC[6] = {1.0f - 0.01f / 2.0f,   1.0f - 0.01f / 5.0f,
                          1.0f - 0.01f / 10.0f,  1.0f - 0.01f / 100.0f,
                          1.0f - 0.01f / 50.0f,  1.0f - 0.01f / 30.0f};
    const float SGN[6] = {-1.f, 1.f, 1.f, -1.f, -1.f, -1.f};

    if (tid == 0) { mbar_init(smem_u32(&mbar[0]), 1); mbar_init(smem_u32(&mbar[1]), 1); }

    {
        float p[6];
#pragma unroll
        for (int t = 0; t < 6; ++t) p[t] = b[t];
        warp_reduce6(p);
        __shared__ float bp6[NWARPS][8];
        if (lane == 0)
#pragma unroll
            for (int t = 0; t < 6; ++t) bp6[wid][t] = p[t];
        __syncthreads();
        if (wid == 0) {
            float q[6];
#pragma unroll
            for (int t = 0; t < 6; ++t) q[t] = (lane < NWARPS) ? bp6[lane][t] : 0.f;
            warp_reduce6(q);
            if (lane < CLUSTERS)
#pragma unroll
                for (int t = 0; t < 6; ++t)
                    dsmem_st(smem_u32(&Bslot[rank][t]), lane, q[t]);
        }
        asm volatile("barrier.cluster.arrive.aligned;" ::: "memory");
        asm volatile("barrier.cluster.wait.aligned;"   ::: "memory");
    }
    float B1 = 0.f, B2 = 0.f;
#pragma unroll
    for (int r = 0; r < CLUSTERS; ++r) { B1 += Bslot[r][1]; B2 += Bslot[r][2]; }

    float u1 = 7.0f * B1;
    float u2 = 9.0f * B2;
    float c1[6];
#pragma unroll
    for (int t = 0; t < 6; ++t) c1[t] = SGN[t] * 0.1f;

    const uint32_t slot_a[2] = { smem_u32(&slot[0][0]), smem_u32(&slot[1][0]) };
    const uint32_t mbar_a[2] = { smem_u32(&mbar[0]),    smem_u32(&mbar[1])    };

    for (int k = 0; k < steps; ++k) {
        const int      par    = k & 1;
        const uint32_t parity = (uint32_t)((k >> 1) & 1);

        if (tid == 0) mbar_expect_tx(mbar_a[par], 8 * 4);

#pragma unroll
        for (int t = 0; t < 6; ++t) c1[t] *= DEC[t];
        u1 *= DEC[1];
        u2 *= DEC[2];

        float acc = c1[0] * b[0];
#pragma unroll
        for (int t = 1; t < 6; ++t) acc = fmaf(c1[t], b[t], acc);
        float w = acc * V;
#pragma unroll
        for (int o = 16; o > 0; o >>= 1)
            w += __shfl_xor_sync(0xffffffffu, w, o);
        if (lane == 0) wpart[wid] = w;
        __syncthreads();
        if (wid == 0) {
            float q = (lane < NWARPS) ? wpart[lane] : 0.f;
#pragma unroll
            for (int o = 8; o > 0; o >>= 1)
                q += __shfl_xor_sync(0xffffffffu, q, o);
            if (lane < CLUSTERS)
                dsmem_st_async(slot_a[par] + 4u * rank, mbar_a[par], lane, q);
        }

        float v  = V;
        float r6[6];
        hh_rates(v, r6);
        mM = mM + DTc * (r6[0] * (1.0f - mM) - r6[1] * mM);
        hH = hH + DTc * (r6[2] * (1.0f - hH) - r6[3] * hH);
        nN = nN + DTc * (r6[4] * (1.0f - nN) - r6[5] * nN);
        float INa = 120.0f * mM * mM * mM * hH * (v - 50.0f);
        float n2  = nN * nN;
        float IK  = 36.0f * n2 * n2 * (v + 77.0f);
        float IL  = 0.3f * (v + 54.387f);
        float hhcur = INa + IK + IL;

        mbar_wait_parity(mbar_a[par], parity);

        float Is = u1 + u2;
        float4 s4a = *reinterpret_cast<const float4*>(&slot[par][0]);
        float4 s4b = *reinterpret_cast<const float4*>(&slot[par][4]);
        Is += s4a.x + s4a.y + s4a.z + s4a.w + s4b.x + s4b.y + s4b.z + s4b.w;

        float vn = v + DTc * (Ie + Is - hhcur);
        unsigned u = __float_as_uint(vn) & 0x7fffffffu;
        if (u > 0x7f800000u) vn = 0.0f;
        else                 vn = fminf(fmaxf(vn, -100.0f), 100.0f);
        V = vn;
        out[(size_t)k * Nn + j] = vn;
    }

    asm volatile("barrier.cluster.arrive.aligned;" ::: "memory");
    asm volatile("barrier.cluster.wait.aligned;"   ::: "memory");
}

// ---------------------------------------------------------------------------
extern "C" void kernel_launch(void* const* d_in, const int* in_sizes, int n_in,
                              void* d_out, int out_size) {
    const float* I_ext = (const float*)d_in[0];
    const float* W     = (const float*)d_in[1];
    const float* V0    = (const float*)d_in[2];
    const float* m0    = (const float*)d_in[3];
    const float* h0    = (const float*)d_in[4];
    const float* n0    = (const float*)d_in[5];
    const float* s0    = (const float*)d_in[6];
    const int*   Ty    = (const int*)d_in[7];
    float* out = (float*)d_out;

    const int steps = out_size / Nn;   // 1000

    dim3 g1(Nn / 256, ROWCHUNKS);
    k_cols_partial<<<g1, 256>>>(W, Ty);
    k_scalar<<<BBLOCKS, 512>>>(s0, I_ext, V0, m0, h0, n0, steps);
    k_write<<<steps, 256>>>(out);
    k_hh<<<CLUSTERS, CTHREADS>>>(I_ext, V0, m0, h0, n0, out, steps);
}